// round 3
// baseline (speedup 1.0000x reference)
#include <cuda_runtime.h>
#include <math.h>

#define Bb 16
#define Tt 2048
#define Hh 512
#define Kk 15
#define BT (Bb*Tt)

// ---------------- scratch (__device__ globals; no allocations allowed) ----------------
__device__ float d_g[(size_t)BT*Hh];   // GLU output (B,T,H)  = 64MB
__device__ float d_alphas[BT];
__device__ float d_weff[Hh];
__device__ float d_beff;
__device__ int   d_nfires[Bb];
__device__ int   d_fire_t[BT];
__device__ float d_dist[BT];
__device__ float d_remain[BT];
__device__ float d_ptn[Bb];

__device__ __forceinline__ float sigm(float v){ return 1.0f/(1.0f + expf(-v)); }

__device__ __forceinline__ float wred(float v){
    #pragma unroll
    for (int o = 16; o > 0; o >>= 1) v += __shfl_down_sync(0xffffffffu, v, o);
    return v;
}

// ---------------- kernel 0: fold pw2 + lin into a single H-vector ----------------
__global__ void weff_kernel(const float* __restrict__ pw2_w, const float* __restrict__ pw2_b,
                            const float* __restrict__ lin_w, const float* __restrict__ lin_b)
{
    int h = threadIdx.x;  // 512 threads
    float s = 0.0f;
    for (int o = 0; o < Hh; o++) s = fmaf(lin_w[o], pw2_w[(size_t)o*Hh + h], s);
    d_weff[h] = s;
    if (h == 0) {
        float bb = lin_b[0];
        for (int o = 0; o < Hh; o++) bb = fmaf(lin_w[o], pw2_b[o], bb);
        d_beff = bb;
    }
}

// ---------------- kernel 1: fp32 GEMM (x @ pw1_w^T) fused with GLU ----------------
// M = 32768, K = 512, per output channel c we need weight rows c and c+H.
// Block tile 128(M) x 64(C), 256 threads, per-thread 8x4 micro-tile with two accum banks.
__launch_bounds__(256)
__global__ void gemm_glu_kernel(const float* __restrict__ x, const float* __restrict__ w,
                                const float* __restrict__ bias)
{
    __shared__ float xs[16][132];   // [k][m], padded (132 = mult of 4 floats, bank-spread)
    __shared__ float was[16][68];   // [k][c] value-half weights
    __shared__ float wbs[16][68];   // [k][c] gate-half weights

    const int tid = threadIdx.x;
    const int tx = tid & 15;        // col group (4 channels)
    const int ty = tid >> 4;        // row group (8 rows)
    const int m0 = blockIdx.x * 128;
    const int c0 = blockIdx.y * 64;

    float acc_a[8][4];
    float acc_b[8][4];
    #pragma unroll
    for (int i = 0; i < 8; i++)
        #pragma unroll
        for (int jj = 0; jj < 4; jj++) { acc_a[i][jj] = 0.0f; acc_b[i][jj] = 0.0f; }

    for (int k0 = 0; k0 < Hh; k0 += 16) {
        __syncthreads();
        // x tile: 128 rows x 16 k = 512 float4s, 2 per thread
        {
            int f = tid;
            #pragma unroll
            for (int q = 0; q < 2; q++, f += 256) {
                int m  = f >> 2;
                int kq = f & 3;
                float4 v = *(const float4*)(x + (size_t)(m0 + m)*Hh + k0 + kq*4);
                xs[kq*4+0][m] = v.x; xs[kq*4+1][m] = v.y;
                xs[kq*4+2][m] = v.z; xs[kq*4+3][m] = v.w;
            }
        }
        // weight tiles: 64 channels x 16 k per half
        {
            int c  = tid >> 2;
            int kq = tid & 3;
            float4 va = *(const float4*)(w + (size_t)(c0 + c)*Hh      + k0 + kq*4);
            float4 vb = *(const float4*)(w + (size_t)(c0 + c + Hh)*Hh + k0 + kq*4);
            was[kq*4+0][c]=va.x; was[kq*4+1][c]=va.y; was[kq*4+2][c]=va.z; was[kq*4+3][c]=va.w;
            wbs[kq*4+0][c]=vb.x; wbs[kq*4+1][c]=vb.y; wbs[kq*4+2][c]=vb.z; wbs[kq*4+3][c]=vb.w;
        }
        __syncthreads();
        #pragma unroll
        for (int kk = 0; kk < 16; kk++) {
            float4 a0 = *(const float4*)&xs[kk][ty*8];
            float4 a1 = *(const float4*)&xs[kk][ty*8+4];
            float4 wa = *(const float4*)&was[kk][tx*4];
            float4 wb = *(const float4*)&wbs[kk][tx*4];
            float av[8]  = {a0.x,a0.y,a0.z,a0.w,a1.x,a1.y,a1.z,a1.w};
            float wav[4] = {wa.x,wa.y,wa.z,wa.w};
            float wbv[4] = {wb.x,wb.y,wb.z,wb.w};
            #pragma unroll
            for (int i = 0; i < 8; i++)
                #pragma unroll
                for (int jj = 0; jj < 4; jj++) {
                    acc_a[i][jj] = fmaf(av[i], wav[jj], acc_a[i][jj]);
                    acc_b[i][jj] = fmaf(av[i], wbv[jj], acc_b[i][jj]);
                }
        }
    }

    float ba[4], bg[4];
    #pragma unroll
    for (int jj = 0; jj < 4; jj++) {
        ba[jj] = bias[c0 + tx*4 + jj];
        bg[jj] = bias[Hh + c0 + tx*4 + jj];
    }
    #pragma unroll
    for (int i = 0; i < 8; i++) {
        int m = m0 + ty*8 + i;
        float4 o;
        o.x = (acc_a[i][0] + ba[0]) * sigm(acc_b[i][0] + bg[0]);
        o.y = (acc_a[i][1] + ba[1]) * sigm(acc_b[i][1] + bg[1]);
        o.z = (acc_a[i][2] + ba[2]) * sigm(acc_b[i][2] + bg[2]);
        o.w = (acc_a[i][3] + ba[3]) * sigm(acc_b[i][3] + bg[3]);
        *(float4*)(d_g + (size_t)m*Hh + c0 + tx*4) = o;
    }
}

// ---------------- kernel 2: depthwise conv + LN + swish + folded pw2/lin -> alphas ----------------
// Block = (T-strip of 64) x batch, 512 threads (one per channel), register sliding window.
__launch_bounds__(512)
__global__ void conv_ln_logit_kernel(const float* __restrict__ dw_w, const float* __restrict__ dw_b,
                                     const float* __restrict__ ln_g, const float* __restrict__ ln_b,
                                     const int* __restrict__ x_lens)
{
    const int ch = threadIdx.x;
    const int b  = blockIdx.y;
    const int t0 = blockIdx.x * 64;
    const int lane = ch & 31, wid = ch >> 5;
    __shared__ float r1[16], r2[16], r3s[16];

    float wk[15];
    #pragma unroll
    for (int k = 0; k < 15; k++) wk[k] = dw_w[ch*Kk + k];
    const float bias = dw_b[ch];
    const float gam  = ln_g[ch];
    const float bet  = ln_b[ch];
    const float weff = d_weff[ch];
    const float beff = d_beff;
    const int   len  = x_lens[b];

    const float* gb = d_g + (size_t)b*Tt*Hh + ch;

    float win[15];
    #pragma unroll
    for (int k = 0; k < 14; k++) {
        int tg = t0 - 14 + k;
        win[k] = (tg >= 0) ? gb[(size_t)tg*Hh] : 0.0f;
    }

    for (int t = 0; t < 64; t++) {
        win[14] = gb[(size_t)(t0 + t)*Hh];
        float c = bias;
        #pragma unroll
        for (int k = 0; k < 15; k++) c = fmaf(win[k], wk[k], c);
        #pragma unroll
        for (int k = 0; k < 14; k++) win[k] = win[k+1];

        // block reduce sum & sumsq
        float s1 = wred(c);
        float s2 = wred(c*c);
        if (lane == 0) { r1[wid] = s1; r2[wid] = s2; }
        __syncthreads();
        if (wid == 0) {
            float a  = (lane < 16) ? r1[lane] : 0.0f;
            float d2 = (lane < 16) ? r2[lane] : 0.0f;
            a  = wred(a);
            d2 = wred(d2);
            if (lane == 0) { r1[0] = a; r2[0] = d2; }
        }
        __syncthreads();
        float mean = r1[0] * (1.0f/512.0f);
        float var  = r2[0] * (1.0f/512.0f) - mean*mean;
        float y  = (c - mean) * rsqrtf(var + 1e-5f) * gam + bet;
        float sw = y * sigm(y);
        float p  = wred(sw * weff);
        if (lane == 0) r3s[wid] = p;
        __syncthreads();
        if (wid == 0) {
            float a = (lane < 16) ? r3s[lane] : 0.0f;
            a = wred(a);
            if (lane == 0 && ch == 0) {
                float logit = a + beff;
                int tg = t0 + t;
                d_alphas[b*Tt + tg] = (tg < len) ? sigm(logit) : 0.0f;
            }
        }
        __syncthreads();
    }
}

// ---------------- kernel 3: per-batch serial CIF scan (exact reference arithmetic) ----------------
__global__ void scan_kernel()
{
    __shared__ float sa[Tt];  // 8KB
    const int b = blockIdx.x;
    for (int i = threadIdx.x; i < Tt; i += blockDim.x) sa[i] = d_alphas[b*Tt + i];
    __syncthreads();
    if (threadIdx.x == 0) {
        float integ = 0.0f, psum = 0.0f;
        int j = 0;
        for (int t = 0; t < Tt; t++) {
            float a = sa[t];
            psum += a;
            float dist = 1.0f - integ;   // FIRE_TH - integrate (pre-add)
            integ = integ + a;           // same op order as reference
            if (integ >= 1.0f) {
                d_fire_t[b*Tt + j] = t;
                d_dist  [b*Tt + j] = dist;
                d_remain[b*Tt + j] = a - dist;
                integ -= 1.0f;
                j++;
            }
        }
        d_nfires[b] = j;
        d_ptn[b] = psum;
    }
}

// ---------------- kernel 4: write all outputs (fired rows, token counts, flipped rows) ----------------
// Every output element written exactly once (d_out is poisoned).
__launch_bounds__(128)
__global__ void output_kernel(const float* __restrict__ x, float* __restrict__ out)
{
    const int b   = blockIdx.y;
    const int j   = blockIdx.x;
    const int tid = threadIdx.x;     // 128 threads, 4 channels each
    float* outF = out;
    float* outP = out + (size_t)Bb*Tt*Hh;
    float* outR = outP + Bb;

    if (j == 0 && tid == 0) outP[b] = d_ptn[b];

    float4 acc = make_float4(0.0f, 0.0f, 0.0f, 0.0f);
    const int nf = d_nfires[b];

    if (j < nf) {
        const float* xb = x + (size_t)b*Tt*Hh + tid*4;
        const int tEnd = d_fire_t[b*Tt + j];
        int t;
        if (j > 0) {
            int   tPrev = d_fire_t[b*Tt + j - 1];
            float wl    = d_remain[b*Tt + j - 1];
            float4 v = *(const float4*)(xb + (size_t)tPrev*Hh);
            acc.x = wl*v.x; acc.y = wl*v.y; acc.z = wl*v.z; acc.w = wl*v.w;
            t = tPrev + 1;
        } else {
            t = 0;
        }
        for (; t < tEnd; t++) {
            float w = d_alphas[b*Tt + t];
            float4 v = *(const float4*)(xb + (size_t)t*Hh);
            acc.x = fmaf(w, v.x, acc.x); acc.y = fmaf(w, v.y, acc.y);
            acc.z = fmaf(w, v.z, acc.z); acc.w = fmaf(w, v.w, acc.w);
        }
        float wd = d_dist[b*Tt + j];
        float4 v = *(const float4*)(xb + (size_t)tEnd*Hh);
        acc.x = fmaf(wd, v.x, acc.x); acc.y = fmaf(wd, v.y, acc.y);
        acc.z = fmaf(wd, v.z, acc.z); acc.w = fmaf(wd, v.w, acc.w);
    }

    *(float4*)(outF + ((size_t)b*Tt + j)*Hh + tid*4) = acc;
    // flipped along H: element ch -> H-1-ch
    *(float4*)(outR + ((size_t)b*Tt + j)*Hh + (Hh - 4 - tid*4)) =
        make_float4(acc.w, acc.z, acc.y, acc.x);
}

// ---------------- launch ----------------
extern "C" void kernel_launch(void* const* d_in, const int* in_sizes, int n_in,
                              void* d_out, int out_size)
{
    const float* x      = (const float*)d_in[0];
    const int*   x_lens = (const int*)  d_in[1];
    const float* pw1_w  = (const float*)d_in[2];
    const float* pw1_b  = (const float*)d_in[3];
    const float* dw_w   = (const float*)d_in[4];
    const float* dw_b   = (const float*)d_in[5];
    const float* ln_g   = (const float*)d_in[6];
    const float* ln_b   = (const float*)d_in[7];
    const float* pw2_w  = (const float*)d_in[8];
    const float* pw2_b  = (const float*)d_in[9];
    const float* lin_w  = (const float*)d_in[10];
    const float* lin_b  = (const float*)d_in[11];
    float* out = (float*)d_out;

    weff_kernel<<<1, Hh>>>(pw2_w, pw2_b, lin_w, lin_b);
    gemm_glu_kernel<<<dim3(BT/128, Hh/64), 256>>>(x, pw1_w, pw1_b);
    conv_ln_logit_kernel<<<dim3(Tt/64, Bb), Hh>>>(dw_w, dw_b, ln_g, ln_b, x_lens);
    scan_kernel<<<Bb, 256>>>();
    output_kernel<<<dim3(Tt, Bb), 128>>>(x, out);
}

// round 4
// speedup vs baseline: 1.0020x; 1.0020x over previous
#include <cuda_runtime.h>
#include <math.h>

#define Bb 16
#define Tt 2048
#define Hh 512
#define Kk 15
#define BT (Bb*Tt)

// ---------------- scratch (__device__ globals; no allocations allowed) ----------------
__device__ float d_g[(size_t)BT*Hh];   // GLU output (B,T,H)  = 64MB
__device__ float d_alphas[BT];
__device__ float d_weff[Hh];
__device__ float d_beff;
__device__ int   d_nfires[Bb];
__device__ int   d_fire_t[BT];
__device__ float d_dist[BT];
__device__ float d_remain[BT];
__device__ float d_ptn[Bb];

__device__ __forceinline__ float sigm(float v){ return 1.0f/(1.0f + expf(-v)); }

__device__ __forceinline__ float wred(float v){
    #pragma unroll
    for (int o = 16; o > 0; o >>= 1) v += __shfl_down_sync(0xffffffffu, v, o);
    return v;
}

// ---------------- kernel 0: fold pw2 + lin into a single H-vector ----------------
__global__ void weff_kernel(const float* __restrict__ pw2_w, const float* __restrict__ pw2_b,
                            const float* __restrict__ lin_w, const float* __restrict__ lin_b)
{
    int h = threadIdx.x;  // 512 threads
    float s = 0.0f;
    for (int o = 0; o < Hh; o++) s = fmaf(lin_w[o], pw2_w[(size_t)o*Hh + h], s);
    d_weff[h] = s;
    if (h == 0) {
        float bb = lin_b[0];
        for (int o = 0; o < Hh; o++) bb = fmaf(lin_w[o], pw2_b[o], bb);
        d_beff = bb;
    }
}

// ---------------- kernel 1: fp32 GEMM (x @ pw1_w^T) fused with GLU ----------------
// M = 32768, K = 512, per output channel c we need weight rows c and c+H.
// Block tile 128(M) x 64(C), 256 threads, per-thread 8x4 micro-tile with two accum banks.
__launch_bounds__(256)
__global__ void gemm_glu_kernel(const float* __restrict__ x, const float* __restrict__ w,
                                const float* __restrict__ bias)
{
    __shared__ float xs[16][132];   // [k][m], padded (132 = mult of 4 floats, bank-spread)
    __shared__ float was[16][68];   // [k][c] value-half weights
    __shared__ float wbs[16][68];   // [k][c] gate-half weights

    const int tid = threadIdx.x;
    const int tx = tid & 15;        // col group (4 channels)
    const int ty = tid >> 4;        // row group (8 rows)
    const int m0 = blockIdx.x * 128;
    const int c0 = blockIdx.y * 64;

    float acc_a[8][4];
    float acc_b[8][4];
    #pragma unroll
    for (int i = 0; i < 8; i++)
        #pragma unroll
        for (int jj = 0; jj < 4; jj++) { acc_a[i][jj] = 0.0f; acc_b[i][jj] = 0.0f; }

    for (int k0 = 0; k0 < Hh; k0 += 16) {
        __syncthreads();
        // x tile: 128 rows x 16 k = 512 float4s, 2 per thread
        {
            int f = tid;
            #pragma unroll
            for (int q = 0; q < 2; q++, f += 256) {
                int m  = f >> 2;
                int kq = f & 3;
                float4 v = *(const float4*)(x + (size_t)(m0 + m)*Hh + k0 + kq*4);
                xs[kq*4+0][m] = v.x; xs[kq*4+1][m] = v.y;
                xs[kq*4+2][m] = v.z; xs[kq*4+3][m] = v.w;
            }
        }
        // weight tiles: 64 channels x 16 k per half
        {
            int c  = tid >> 2;
            int kq = tid & 3;
            float4 va = *(const float4*)(w + (size_t)(c0 + c)*Hh      + k0 + kq*4);
            float4 vb = *(const float4*)(w + (size_t)(c0 + c + Hh)*Hh + k0 + kq*4);
            was[kq*4+0][c]=va.x; was[kq*4+1][c]=va.y; was[kq*4+2][c]=va.z; was[kq*4+3][c]=va.w;
            wbs[kq*4+0][c]=vb.x; wbs[kq*4+1][c]=vb.y; wbs[kq*4+2][c]=vb.z; wbs[kq*4+3][c]=vb.w;
        }
        __syncthreads();
        #pragma unroll
        for (int kk = 0; kk < 16; kk++) {
            float4 a0 = *(const float4*)&xs[kk][ty*8];
            float4 a1 = *(const float4*)&xs[kk][ty*8+4];
            float4 wa = *(const float4*)&was[kk][tx*4];
            float4 wb = *(const float4*)&wbs[kk][tx*4];
            float av[8]  = {a0.x,a0.y,a0.z,a0.w,a1.x,a1.y,a1.z,a1.w};
            float wav[4] = {wa.x,wa.y,wa.z,wa.w};
            float wbv[4] = {wb.x,wb.y,wb.z,wb.w};
            #pragma unroll
            for (int i = 0; i < 8; i++)
                #pragma unroll
                for (int jj = 0; jj < 4; jj++) {
                    acc_a[i][jj] = fmaf(av[i], wav[jj], acc_a[i][jj]);
                    acc_b[i][jj] = fmaf(av[i], wbv[jj], acc_b[i][jj]);
                }
        }
    }

    float ba[4], bg[4];
    #pragma unroll
    for (int jj = 0; jj < 4; jj++) {
        ba[jj] = bias[c0 + tx*4 + jj];
        bg[jj] = bias[Hh + c0 + tx*4 + jj];
    }
    #pragma unroll
    for (int i = 0; i < 8; i++) {
        int m = m0 + ty*8 + i;
        float4 o;
        o.x = (acc_a[i][0] + ba[0]) * sigm(acc_b[i][0] + bg[0]);
        o.y = (acc_a[i][1] + ba[1]) * sigm(acc_b[i][1] + bg[1]);
        o.z = (acc_a[i][2] + ba[2]) * sigm(acc_b[i][2] + bg[2]);
        o.w = (acc_a[i][3] + ba[3]) * sigm(acc_b[i][3] + bg[3]);
        *(float4*)(d_g + (size_t)m*Hh + c0 + tx*4) = o;
    }
}

// ---------------- kernel 2: depthwise conv + LN + swish + folded pw2/lin -> alphas ----------------
// Block = (T-strip of 64) x batch, 512 threads (one per channel), register sliding window.
__launch_bounds__(512)
__global__ void conv_ln_logit_kernel(const float* __restrict__ dw_w, const float* __restrict__ dw_b,
                                     const float* __restrict__ ln_g, const float* __restrict__ ln_b,
                                     const int* __restrict__ x_lens)
{
    const int ch = threadIdx.x;
    const int b  = blockIdx.y;
    const int t0 = blockIdx.x * 64;
    const int lane = ch & 31, wid = ch >> 5;
    __shared__ float r1[16], r2[16], r3s[16];

    float wk[15];
    #pragma unroll
    for (int k = 0; k < 15; k++) wk[k] = dw_w[ch*Kk + k];
    const float bias = dw_b[ch];
    const float gam  = ln_g[ch];
    const float bet  = ln_b[ch];
    const float weff = d_weff[ch];
    const float beff = d_beff;
    const int   len  = x_lens[b];

    const float* gb = d_g + (size_t)b*Tt*Hh + ch;

    float win[15];
    #pragma unroll
    for (int k = 0; k < 14; k++) {
        int tg = t0 - 14 + k;
        win[k] = (tg >= 0) ? gb[(size_t)tg*Hh] : 0.0f;
    }

    for (int t = 0; t < 64; t++) {
        win[14] = gb[(size_t)(t0 + t)*Hh];
        float c = bias;
        #pragma unroll
        for (int k = 0; k < 15; k++) c = fmaf(win[k], wk[k], c);
        #pragma unroll
        for (int k = 0; k < 14; k++) win[k] = win[k+1];

        // block reduce sum & sumsq
        float s1 = wred(c);
        float s2 = wred(c*c);
        if (lane == 0) { r1[wid] = s1; r2[wid] = s2; }
        __syncthreads();
        if (wid == 0) {
            float a  = (lane < 16) ? r1[lane] : 0.0f;
            float d2 = (lane < 16) ? r2[lane] : 0.0f;
            a  = wred(a);
            d2 = wred(d2);
            if (lane == 0) { r1[0] = a; r2[0] = d2; }
        }
        __syncthreads();
        float mean = r1[0] * (1.0f/512.0f);
        float var  = r2[0] * (1.0f/512.0f) - mean*mean;
        float y  = (c - mean) * rsqrtf(var + 1e-5f) * gam + bet;
        float sw = y * sigm(y);
        float p  = wred(sw * weff);
        if (lane == 0) r3s[wid] = p;
        __syncthreads();
        if (wid == 0) {
            float a = (lane < 16) ? r3s[lane] : 0.0f;
            a = wred(a);
            if (lane == 0 && ch == 0) {
                float logit = a + beff;
                int tg = t0 + t;
                d_alphas[b*Tt + tg] = (tg < len) ? sigm(logit) : 0.0f;
            }
        }
        __syncthreads();
    }
}

// ---------------- kernel 3: per-batch serial CIF scan (exact reference arithmetic) ----------------
__global__ void scan_kernel()
{
    __shared__ float sa[Tt];  // 8KB
    const int b = blockIdx.x;
    for (int i = threadIdx.x; i < Tt; i += blockDim.x) sa[i] = d_alphas[b*Tt + i];
    __syncthreads();
    if (threadIdx.x == 0) {
        float integ = 0.0f, psum = 0.0f;
        int j = 0;
        for (int t = 0; t < Tt; t++) {
            float a = sa[t];
            psum += a;
            float dist = 1.0f - integ;   // FIRE_TH - integrate (pre-add)
            integ = integ + a;           // same op order as reference
            if (integ >= 1.0f) {
                d_fire_t[b*Tt + j] = t;
                d_dist  [b*Tt + j] = dist;
                d_remain[b*Tt + j] = a - dist;
                integ -= 1.0f;
                j++;
            }
        }
        d_nfires[b] = j;
        d_ptn[b] = psum;
    }
}

// ---------------- kernel 4: write all outputs (fired rows, token counts, flipped rows) ----------------
// Every output element written exactly once (d_out is poisoned).
__launch_bounds__(128)
__global__ void output_kernel(const float* __restrict__ x, float* __restrict__ out)
{
    const int b   = blockIdx.y;
    const int j   = blockIdx.x;
    const int tid = threadIdx.x;     // 128 threads, 4 channels each
    float* outF = out;
    float* outP = out + (size_t)Bb*Tt*Hh;
    float* outR = outP + Bb;

    if (j == 0 && tid == 0) outP[b] = d_ptn[b];

    float4 acc = make_float4(0.0f, 0.0f, 0.0f, 0.0f);
    const int nf = d_nfires[b];

    if (j < nf) {
        const float* xb = x + (size_t)b*Tt*Hh + tid*4;
        const int tEnd = d_fire_t[b*Tt + j];
        int t;
        if (j > 0) {
            int   tPrev = d_fire_t[b*Tt + j - 1];
            float wl    = d_remain[b*Tt + j - 1];
            float4 v = *(const float4*)(xb + (size_t)tPrev*Hh);
            acc.x = wl*v.x; acc.y = wl*v.y; acc.z = wl*v.z; acc.w = wl*v.w;
            t = tPrev + 1;
        } else {
            t = 0;
        }
        for (; t < tEnd; t++) {
            float w = d_alphas[b*Tt + t];
            float4 v = *(const float4*)(xb + (size_t)t*Hh);
            acc.x = fmaf(w, v.x, acc.x); acc.y = fmaf(w, v.y, acc.y);
            acc.z = fmaf(w, v.z, acc.z); acc.w = fmaf(w, v.w, acc.w);
        }
        float wd = d_dist[b*Tt + j];
        float4 v = *(const float4*)(xb + (size_t)tEnd*Hh);
        acc.x = fmaf(wd, v.x, acc.x); acc.y = fmaf(wd, v.y, acc.y);
        acc.z = fmaf(wd, v.z, acc.z); acc.w = fmaf(wd, v.w, acc.w);
    }

    *(float4*)(outF + ((size_t)b*Tt + j)*Hh + tid*4) = acc;
    // flipped along H: element ch -> H-1-ch
    *(float4*)(outR + ((size_t)b*Tt + j)*Hh + (Hh - 4 - tid*4)) =
        make_float4(acc.w, acc.z, acc.y, acc.x);
}

// ---------------- launch ----------------
extern "C" void kernel_launch(void* const* d_in, const int* in_sizes, int n_in,
                              void* d_out, int out_size)
{
    const float* x      = (const float*)d_in[0];
    const int*   x_lens = (const int*)  d_in[1];
    const float* pw1_w  = (const float*)d_in[2];
    const float* pw1_b  = (const float*)d_in[3];
    const float* dw_w   = (const float*)d_in[4];
    const float* dw_b   = (const float*)d_in[5];
    const float* ln_g   = (const float*)d_in[6];
    const float* ln_b   = (const float*)d_in[7];
    const float* pw2_w  = (const float*)d_in[8];
    const float* pw2_b  = (const float*)d_in[9];
    const float* lin_w  = (const float*)d_in[10];
    const float* lin_b  = (const float*)d_in[11];
    float* out = (float*)d_out;

    weff_kernel<<<1, Hh>>>(pw2_w, pw2_b, lin_w, lin_b);
    gemm_glu_kernel<<<dim3(BT/128, Hh/64), 256>>>(x, pw1_w, pw1_b);
    conv_ln_logit_kernel<<<dim3(Tt/64, Bb), Hh>>>(dw_w, dw_b, ln_g, ln_b, x_lens);
    scan_kernel<<<Bb, 256>>>();
    output_kernel<<<dim3(Tt, Bb), 128>>>(x, out);
}

// round 6
// speedup vs baseline: 1.1473x; 1.1450x over previous
#include <cuda_runtime.h>
#include <math.h>
#include <stdint.h>

#define Bb 16
#define Tt 2048
#define Hh 512
#define Kk 15
#define BT (Bb*Tt)

// ---- GEMM tiling ----
#define GM 128          // M per block
#define GN 128          // interleaved N per block (64 value + 64 gate cols)
#define KC 32           // K per pipeline chunk
#define NCHUNK (Hh/KC)  // 16
#define LDP 36          // padded row length (floats): bank-conflict-free
#define BUFS (GM*LDP)   // 4608 floats per buffer per operand
#define SMEM_DYN (4*BUFS*4)   // As[2]+Bs[2] = 73728 bytes

// ---------------- scratch (__device__ globals) ----------------
__device__ float d_g[(size_t)BT*Hh];   // GLU output (B,T,H) 64MB
__device__ float d_alphas[BT];
__device__ float d_weff[Hh];
__device__ float d_wpart[32*Hh];
__device__ float d_beff;
__device__ int   d_nfires[Bb];
__device__ int   d_fire_t[BT];
__device__ float d_dist[BT];
__device__ float d_remain[BT];
__device__ float d_ptn[Bb];

__device__ __forceinline__ float sigm(float v){ return 1.0f/(1.0f + expf(-v)); }

__device__ __forceinline__ float wred(float v){
    #pragma unroll
    for (int o = 16; o > 0; o >>= 1) v += __shfl_down_sync(0xffffffffu, v, o);
    return v;
}

__device__ __forceinline__ uint32_t f2tf32(float v){
    uint32_t r;
    asm("cvt.rna.tf32.f32 %0, %1;" : "=r"(r) : "f"(v));
    return r;
}
__device__ __forceinline__ void tf32_split(float v, uint32_t& h, uint32_t& l){
    h = f2tf32(v);
    l = f2tf32(v - __uint_as_float(h));
}

__device__ __forceinline__ void mma_tf32(float* c, const uint32_t* a, const uint32_t* b){
    asm volatile(
        "mma.sync.aligned.m16n8k8.row.col.f32.tf32.tf32.f32 "
        "{%0,%1,%2,%3}, {%4,%5,%6,%7}, {%8,%9}, {%0,%1,%2,%3};"
        : "+f"(c[0]), "+f"(c[1]), "+f"(c[2]), "+f"(c[3])
        : "r"(a[0]), "r"(a[1]), "r"(a[2]), "r"(a[3]), "r"(b[0]), "r"(b[1]));
}

// ---------------- kernels 0a/0b: fold pw2+lin into w_eff (parallel GEMV) ----------------
__global__ void weff_part(const float* __restrict__ pw2_w, const float* __restrict__ lin_w)
{
    int t = threadIdx.x, j = blockIdx.x;   // 32 blocks x 512 threads
    float s = 0.0f;
    #pragma unroll
    for (int o = j*16; o < j*16 + 16; o++)
        s = fmaf(lin_w[o], pw2_w[(size_t)o*Hh + t], s);
    d_wpart[j*Hh + t] = s;
}
__global__ void weff_sum(const float* __restrict__ pw2_b, const float* __restrict__ lin_w,
                         const float* __restrict__ lin_b)
{
    int t = threadIdx.x;
    float s = 0.0f;
    #pragma unroll
    for (int j = 0; j < 32; j++) s += d_wpart[j*Hh + t];
    d_weff[t] = s;
    if (t == 0) {
        float bb = lin_b[0];
        for (int o = 0; o < Hh; o++) bb = fmaf(lin_w[o], pw2_b[o], bb);
        d_beff = bb;
    }
}

// ---------------- kernel 1: tf32x3 mma.sync GEMM (x @ pw1_w^T) fused with GLU ----------------
// Logical N=1024 (value/gate interleaved pairs). Block 128x128, 8 warps,
// warp tile 32(M) x 64(N) = 2x8 m16n8k8 tiles. tf32x3: ah*bh + ah*bl + al*bh.
__global__ void __launch_bounds__(256, 1)
gemm_glu_mma(const float* __restrict__ x, const float* __restrict__ w,
             const float* __restrict__ bias)
{
    extern __shared__ float sm[];
    float* As = sm;            // [2][128][36]
    float* Bs = sm + 2*BUFS;   // [2][128][36]

    const int tid  = threadIdx.x;
    const int wid  = tid >> 5;
    const int lane = tid & 31;
    const int gid  = lane >> 2;      // 0..7
    const int tig  = lane & 3;       // 0..3
    const int mB = blockIdx.y * GM;
    const int nB = blockIdx.x * GN;  // interleaved col base
    const int cB = nB >> 1;          // channel base
    const int mw = (wid & 3) * 32;   // warp M offset
    const int nw = (wid >> 2) * 64;  // warp N offset (interleaved)

    float acc[2][8][4];
    #pragma unroll
    for (int mt = 0; mt < 2; mt++)
        #pragma unroll
        for (int nt = 0; nt < 8; nt++)
            #pragma unroll
            for (int e = 0; e < 4; e++) acc[mt][nt][e] = 0.0f;

    float4 ra[4], rb[4];

    // ---- global load of one K-chunk into registers ----
    #define LDG_CHUNK(k0) do { \
        _Pragma("unroll") \
        for (int t = 0; t < 4; t++) { \
            int idx = tid + t*256; \
            int r = idx >> 3, kq = idx & 7; \
            ra[t] = *(const float4*)(x + (size_t)(mB + r)*Hh + (k0) + kq*4); \
            int nq = nB + r; \
            int wr = (nq >> 1) + (nq & 1)*Hh; \
            rb[t] = *(const float4*)(w + (size_t)wr*Hh + (k0) + kq*4); \
        } \
    } while(0)

    #define STS_CHUNK(buf) do { \
        _Pragma("unroll") \
        for (int t = 0; t < 4; t++) { \
            int idx = tid + t*256; \
            int r = idx >> 3, kq = idx & 7; \
            *(float4*)(As + (buf)*BUFS + r*LDP + kq*4) = ra[t]; \
            *(float4*)(Bs + (buf)*BUFS + r*LDP + kq*4) = rb[t]; \
        } \
    } while(0)

    #define COMPUTE(buf) do { \
        const float* Ab = As + (buf)*BUFS + mw*LDP; \
        const float* Bw = Bs + (buf)*BUFS + nw*LDP; \
        _Pragma("unroll") \
        for (int kk = 0; kk < 4; kk++) { \
            const int kc = kk*8 + tig; \
            uint32_t ah[2][4], al[2][4]; \
            _Pragma("unroll") \
            for (int mt = 0; mt < 2; mt++) { \
                const int r0 = mt*16 + gid; \
                tf32_split(Ab[r0*LDP + kc],        ah[mt][0], al[mt][0]); \
                tf32_split(Ab[(r0+8)*LDP + kc],    ah[mt][1], al[mt][1]); \
                tf32_split(Ab[r0*LDP + kc + 4],    ah[mt][2], al[mt][2]); \
                tf32_split(Ab[(r0+8)*LDP + kc + 4],ah[mt][3], al[mt][3]); \
            } \
            uint32_t bh[8][2], bl[8][2]; \
            _Pragma("unroll") \
            for (int nt = 0; nt < 8; nt++) { \
                const int n = nt*8 + gid; \
                tf32_split(Bw[n*LDP + kc],     bh[nt][0], bl[nt][0]); \
                tf32_split(Bw[n*LDP + kc + 4], bh[nt][1], bl[nt][1]); \
            } \
            _Pragma("unroll") \
            for (int nt = 0; nt < 8; nt++) { \
                mma_tf32(acc[0][nt], ah[0], bh[nt]); \
                mma_tf32(acc[1][nt], ah[1], bh[nt]); \
            } \
            _Pragma("unroll") \
            for (int nt = 0; nt < 8; nt++) { \
                mma_tf32(acc[0][nt], ah[0], bl[nt]); \
                mma_tf32(acc[1][nt], ah[1], bl[nt]); \
            } \
            _Pragma("unroll") \
            for (int nt = 0; nt < 8; nt++) { \
                mma_tf32(acc[0][nt], al[0], bh[nt]); \
                mma_tf32(acc[1][nt], al[1], bh[nt]); \
            } \
        } \
    } while(0)

    LDG_CHUNK(0);
    STS_CHUNK(0);
    __syncthreads();

    #pragma unroll 1
    for (int c = 0; c < NCHUNK; c++) {
        if (c + 1 < NCHUNK) LDG_CHUNK((c + 1)*KC);
        COMPUTE(c & 1);
        __syncthreads();
        if (c + 1 < NCHUNK) {
            STS_CHUNK((c + 1) & 1);
            __syncthreads();
        }
    }

    // ---- epilogue: GLU on (even,odd) col pairs -> d_g ----
    #pragma unroll
    for (int nt = 0; nt < 8; nt++) {
        const int ch = cB + (nw >> 1) + nt*4 + tig;
        const float bv = bias[ch];
        const float bg = bias[Hh + ch];
        #pragma unroll
        for (int mt = 0; mt < 2; mt++) {
            const int m0 = mB + mw + mt*16 + gid;
            float g0 = (acc[mt][nt][0] + bv) * sigm(acc[mt][nt][1] + bg);
            float g2 = (acc[mt][nt][2] + bv) * sigm(acc[mt][nt][3] + bg);
            d_g[(size_t)m0*Hh + ch]       = g0;
            d_g[(size_t)(m0 + 8)*Hh + ch] = g2;
        }
    }
}

// ---------------- kernel 2: depthwise conv + LN + swish + folded pw2/lin -> alphas ----------------
__launch_bounds__(512)
__global__ void conv_ln_logit_kernel(const float* __restrict__ dw_w, const float* __restrict__ dw_b,
                                     const float* __restrict__ ln_g, const float* __restrict__ ln_b,
                                     const int* __restrict__ x_lens)
{
    const int ch = threadIdx.x;
    const int b  = blockIdx.y;
    const int t0 = blockIdx.x * 64;
    const int lane = ch & 31, wid = ch >> 5;
    __shared__ float r1[16], r2[16], r3s[16];

    float wk[15];
    #pragma unroll
    for (int k = 0; k < 15; k++) wk[k] = dw_w[ch*Kk + k];
    const float bias = dw_b[ch];
    const float gam  = ln_g[ch];
    const float bet  = ln_b[ch];
    const float weff = d_weff[ch];
    const float beff = d_beff;
    const int   len  = x_lens[b];

    const float* gb = d_g + (size_t)b*Tt*Hh + ch;

    float win[15];
    #pragma unroll
    for (int k = 0; k < 14; k++) {
        int tg = t0 - 14 + k;
        win[k] = (tg >= 0) ? gb[(size_t)tg*Hh] : 0.0f;
    }

    for (int t = 0; t < 64; t++) {
        win[14] = gb[(size_t)(t0 + t)*Hh];
        float c = bias;
        #pragma unroll
        for (int k = 0; k < 15; k++) c = fmaf(win[k], wk[k], c);
        #pragma unroll
        for (int k = 0; k < 14; k++) win[k] = win[k+1];

        float s1 = wred(c);
        float s2 = wred(c*c);
        if (lane == 0) { r1[wid] = s1; r2[wid] = s2; }
        __syncthreads();
        if (wid == 0) {
            float a  = (lane < 16) ? r1[lane] : 0.0f;
            float d2 = (lane < 16) ? r2[lane] : 0.0f;
            a  = wred(a);
            d2 = wred(d2);
            if (lane == 0) { r1[0] = a; r2[0] = d2; }
        }
        __syncthreads();
        float mean = r1[0] * (1.0f/512.0f);
        float var  = r2[0] * (1.0f/512.0f) - mean*mean;
        float y  = (c - mean) * rsqrtf(var + 1e-5f) * gam + bet;
        float sw = y * sigm(y);
        float p  = wred(sw * weff);
        if (lane == 0) r3s[wid] = p;
        __syncthreads();
        if (wid == 0) {
            float a = (lane < 16) ? r3s[lane] : 0.0f;
            a = wred(a);
            if (lane == 0 && ch == 0) {
                float logit = a + beff;
                int tg = t0 + t;
                d_alphas[b*Tt + tg] = (tg < len) ? sigm(logit) : 0.0f;
            }
        }
        __syncthreads();
    }
}

// ---------------- kernel 3: per-batch serial CIF scan (short dependency chain) ----------------
__global__ void scan_kernel()
{
    __shared__ float sa[Tt];
    const int b = blockIdx.x;
    for (int i = threadIdx.x; i < Tt; i += blockDim.x) sa[i] = d_alphas[b*Tt + i];
    __syncthreads();
    if (threadIdx.x == 0) {
        float integ = 0.0f, psum = 0.0f;
        int j = 0;
        for (int t = 0; t < Tt; t++) {
            float a = sa[t];
            psum += a;
            float tt = integ + a;             // reference: integrate + alpha
            bool fire = (tt >= 1.0f);
            if (fire) {
                float dist = 1.0f - integ;    // FIRE_TH - integrate(pre)
                d_fire_t[b*Tt + j] = t;
                d_dist  [b*Tt + j] = dist;
                d_remain[b*Tt + j] = a - dist;
                j++;
            }
            integ = fire ? (tt - 1.0f) : tt;  // short FADD/FSETP/FSEL chain
        }
        d_nfires[b] = j;
        d_ptn[b] = psum;
    }
}

// ---------------- kernel 4: write all outputs ----------------
__launch_bounds__(128)
__global__ void output_kernel(const float* __restrict__ x, float* __restrict__ out)
{
    const int b   = blockIdx.y;
    const int j   = blockIdx.x;
    const int tid = threadIdx.x;
    float* outF = out;
    float* outP = out + (size_t)Bb*Tt*Hh;
    float* outR = outP + Bb;

    if (j == 0 && tid == 0) outP[b] = d_ptn[b];

    float4 acc = make_float4(0.0f, 0.0f, 0.0f, 0.0f);
    const int nf = d_nfires[b];

    if (j < nf) {
        const float* xb = x + (size_t)b*Tt*Hh + tid*4;
        const int tEnd = d_fire_t[b*Tt + j];
        int t;
        if (j > 0) {
            int   tPrev = d_fire_t[b*Tt + j - 1];
            float wl    = d_remain[b*Tt + j - 1];
            float4 v = *(const float4*)(xb + (size_t)tPrev*Hh);
            acc.x = wl*v.x; acc.y = wl*v.y; acc.z = wl*v.z; acc.w = wl*v.w;
            t = tPrev + 1;
        } else {
            t = 0;
        }
        for (; t < tEnd; t++) {
            float w = d_alphas[b*Tt + t];
            float4 v = *(const float4*)(xb + (size_t)t*Hh);
            acc.x = fmaf(w, v.x, acc.x); acc.y = fmaf(w, v.y, acc.y);
            acc.z = fmaf(w, v.z, acc.z); acc.w = fmaf(w, v.w, acc.w);
        }
        float wd = d_dist[b*Tt + j];
        float4 v = *(const float4*)(xb + (size_t)tEnd*Hh);
        acc.x = fmaf(wd, v.x, acc.x); acc.y = fmaf(wd, v.y, acc.y);
        acc.z = fmaf(wd, v.z, acc.z); acc.w = fmaf(wd, v.w, acc.w);
    }

    *(float4*)(outF + ((size_t)b*Tt + j)*Hh + tid*4) = acc;
    *(float4*)(outR + ((size_t)b*Tt + j)*Hh + (Hh - 4 - tid*4)) =
        make_float4(acc.w, acc.z, acc.y, acc.x);
}

// ---------------- launch ----------------
extern "C" void kernel_launch(void* const* d_in, const int* in_sizes, int n_in,
                              void* d_out, int out_size)
{
    const float* x      = (const float*)d_in[0];
    const int*   x_lens = (const int*)  d_in[1];
    const float* pw1_w  = (const float*)d_in[2];
    const float* pw1_b  = (const float*)d_in[3];
    const float* dw_w   = (const float*)d_in[4];
    const float* dw_b   = (const float*)d_in[5];
    const float* ln_g   = (const float*)d_in[6];
    const float* ln_b   = (const float*)d_in[7];
    const float* pw2_w  = (const float*)d_in[8];
    const float* pw2_b  = (const float*)d_in[9];
    const float* lin_w  = (const float*)d_in[10];
    const float* lin_b  = (const float*)d_in[11];
    float* out = (float*)d_out;

    cudaFuncSetAttribute(gemm_glu_mma, cudaFuncAttributeMaxDynamicSharedMemorySize, SMEM_DYN);

    weff_part<<<32, Hh>>>(pw2_w, lin_w);
    weff_sum<<<1, Hh>>>(pw2_b, lin_w, lin_b);
    gemm_glu_mma<<<dim3(8, BT/GM), 256, SMEM_DYN>>>(x, pw1_w, pw1_b);
    conv_ln_logit_kernel<<<dim3(Tt/64, Bb), Hh>>>(dw_w, dw_b, ln_g, ln_b, x_lens);
    scan_kernel<<<Bb, 256>>>();
    output_kernel<<<dim3(Tt, Bb), 128>>>(x, out);
}

// round 7
// speedup vs baseline: 1.2896x; 1.1240x over previous
#include <cuda_runtime.h>
#include <math.h>
#include <stdint.h>

#define Bb 16
#define Tt 2048
#define Hh 512
#define Kk 15
#define BT (Bb*Tt)

// ---- GEMM tiling ----
#define GM 128          // M per block
#define GN 128          // interleaved N per block (64 value + 64 gate cols)
#define KC 32           // K per pipeline chunk
#define NCHUNK (Hh/KC)  // 16
#define LDP 36          // padded row length: bank-conflict-free
#define BUFS (GM*LDP)   // 4608 words per buffer
// smem: AH[2] AL[2] BH[2] BL[2] -> 8 buffers
#define SMEM_GEMM (8*BUFS*4)   // 147456 bytes

// ---- conv tiling ----
#define CT 32
#define SMEM_CONV ((CT*Hh + 3*Hh)*4)   // cs + (ln_g, ln_b, weff) = 71680

// ---------------- scratch (__device__ globals) ----------------
__device__ float d_g[(size_t)BT*Hh];   // GLU output (B,T,H) 64MB
__device__ float d_alphas[BT];
__device__ float d_weff[Hh];
__device__ float d_wpart[32*Hh];
__device__ float d_beff;
__device__ int   d_nfires[Bb];
__device__ int   d_fire_t[BT];
__device__ float d_dist[BT];
__device__ float d_remain[BT];
__device__ float d_ptn[Bb];

__device__ __forceinline__ float sigm(float v){ return 1.0f/(1.0f + expf(-v)); }

__device__ __forceinline__ float bfred(float v){        // butterfly: all lanes get sum
    #pragma unroll
    for (int o = 16; o > 0; o >>= 1) v += __shfl_xor_sync(0xffffffffu, v, o);
    return v;
}

__device__ __forceinline__ uint32_t f2tf32(float v){
    uint32_t r;
    asm("cvt.rna.tf32.f32 %0, %1;" : "=r"(r) : "f"(v));
    return r;
}
__device__ __forceinline__ void tf32_split(float v, uint32_t& h, uint32_t& l){
    h = f2tf32(v);
    l = f2tf32(v - __uint_as_float(h));
}

__device__ __forceinline__ void mma_tf32(float* c, const uint32_t* a, const uint32_t* b){
    asm volatile(
        "mma.sync.aligned.m16n8k8.row.col.f32.tf32.tf32.f32 "
        "{%0,%1,%2,%3}, {%4,%5,%6,%7}, {%8,%9}, {%0,%1,%2,%3};"
        : "+f"(c[0]), "+f"(c[1]), "+f"(c[2]), "+f"(c[3])
        : "r"(a[0]), "r"(a[1]), "r"(a[2]), "r"(a[3]), "r"(b[0]), "r"(b[1]));
}

// ---------------- kernels 0a/0b: fold pw2+lin into w_eff ----------------
__global__ void weff_part(const float* __restrict__ pw2_w, const float* __restrict__ lin_w)
{
    int t = threadIdx.x, j = blockIdx.x;
    float s = 0.0f;
    #pragma unroll
    for (int o = j*16; o < j*16 + 16; o++)
        s = fmaf(lin_w[o], pw2_w[(size_t)o*Hh + t], s);
    d_wpart[j*Hh + t] = s;
}
__global__ void weff_sum(const float* __restrict__ pw2_b, const float* __restrict__ lin_w,
                         const float* __restrict__ lin_b)
{
    int t = threadIdx.x;
    float s = 0.0f;
    #pragma unroll
    for (int j = 0; j < 32; j++) s += d_wpart[j*Hh + t];
    d_weff[t] = s;
    if (t == 0) {
        float bb = lin_b[0];
        for (int o = 0; o < Hh; o++) bb = fmaf(lin_w[o], pw2_b[o], bb);
        d_beff = bb;
    }
}

// ---------------- kernel 1: tf32x3 mma.sync GEMM + GLU, producer-side split ----------------
__global__ void __launch_bounds__(256, 1)
gemm_glu_mma(const float* __restrict__ x, const float* __restrict__ w,
             const float* __restrict__ bias)
{
    extern __shared__ uint32_t smg[];
    uint32_t* AH = smg;              // [2][BUFS]
    uint32_t* AL = smg + 2*BUFS;
    uint32_t* BH = smg + 4*BUFS;
    uint32_t* BL = smg + 6*BUFS;

    const int tid  = threadIdx.x;
    const int wid  = tid >> 5;
    const int lane = tid & 31;
    const int gid  = lane >> 2;
    const int tig  = lane & 3;
    const int mB = blockIdx.y * GM;
    const int nB = blockIdx.x * GN;
    const int cB = nB >> 1;
    const int mw = (wid & 3) * 32;
    const int nw = (wid >> 2) * 64;

    float acc[2][8][4];
    #pragma unroll
    for (int mt = 0; mt < 2; mt++)
        #pragma unroll
        for (int nt = 0; nt < 8; nt++)
            #pragma unroll
            for (int e = 0; e < 4; e++) acc[mt][nt][e] = 0.0f;

    float4 ra[4], rb[4];

    #define LDG_CHUNK(k0) do { \
        _Pragma("unroll") \
        for (int t = 0; t < 4; t++) { \
            int idx = tid + t*256; \
            int r = idx >> 3, kq = idx & 7; \
            ra[t] = *(const float4*)(x + (size_t)(mB + r)*Hh + (k0) + kq*4); \
            int nq = nB + r; \
            int wr = (nq >> 1) + (nq & 1)*Hh; \
            rb[t] = *(const float4*)(w + (size_t)wr*Hh + (k0) + kq*4); \
        } \
    } while(0)

    #define STS_CHUNK(buf) do { \
        _Pragma("unroll") \
        for (int t = 0; t < 4; t++) { \
            int idx = tid + t*256; \
            int r = idx >> 3, kq = idx & 7; \
            uint32_t o = (buf)*BUFS + r*LDP + kq*4; \
            uint32_t h0,h1,h2,h3,l0,l1,l2,l3; \
            tf32_split(ra[t].x,h0,l0); tf32_split(ra[t].y,h1,l1); \
            tf32_split(ra[t].z,h2,l2); tf32_split(ra[t].w,h3,l3); \
            *(uint4*)(AH + o) = make_uint4(h0,h1,h2,h3); \
            *(uint4*)(AL + o) = make_uint4(l0,l1,l2,l3); \
            tf32_split(rb[t].x,h0,l0); tf32_split(rb[t].y,h1,l1); \
            tf32_split(rb[t].z,h2,l2); tf32_split(rb[t].w,h3,l3); \
            *(uint4*)(BH + o) = make_uint4(h0,h1,h2,h3); \
            *(uint4*)(BL + o) = make_uint4(l0,l1,l2,l3); \
        } \
    } while(0)

    #define COMPUTE(buf) do { \
        const uint32_t* AHp = AH + (buf)*BUFS + mw*LDP; \
        const uint32_t* ALp = AL + (buf)*BUFS + mw*LDP; \
        const uint32_t* BHp = BH + (buf)*BUFS + nw*LDP; \
        const uint32_t* BLp = BL + (buf)*BUFS + nw*LDP; \
        _Pragma("unroll") \
        for (int kk = 0; kk < 4; kk++) { \
            const int kc = kk*8 + tig; \
            uint32_t ah[2][4], al[2][4]; \
            _Pragma("unroll") \
            for (int mt = 0; mt < 2; mt++) { \
                const int r0 = mt*16 + gid; \
                ah[mt][0] = AHp[r0*LDP + kc];         al[mt][0] = ALp[r0*LDP + kc]; \
                ah[mt][1] = AHp[(r0+8)*LDP + kc];     al[mt][1] = ALp[(r0+8)*LDP + kc]; \
                ah[mt][2] = AHp[r0*LDP + kc + 4];     al[mt][2] = ALp[r0*LDP + kc + 4]; \
                ah[mt][3] = AHp[(r0+8)*LDP + kc + 4]; al[mt][3] = ALp[(r0+8)*LDP + kc + 4]; \
            } \
            uint32_t bh[8][2], bl[8][2]; \
            _Pragma("unroll") \
            for (int nt = 0; nt < 8; nt++) { \
                const int n = nt*8 + gid; \
                bh[nt][0] = BHp[n*LDP + kc];     bl[nt][0] = BLp[n*LDP + kc]; \
                bh[nt][1] = BHp[n*LDP + kc + 4]; bl[nt][1] = BLp[n*LDP + kc + 4]; \
            } \
            _Pragma("unroll") \
            for (int nt = 0; nt < 8; nt++) { \
                mma_tf32(acc[0][nt], ah[0], bh[nt]); \
                mma_tf32(acc[1][nt], ah[1], bh[nt]); \
            } \
            _Pragma("unroll") \
            for (int nt = 0; nt < 8; nt++) { \
                mma_tf32(acc[0][nt], ah[0], bl[nt]); \
                mma_tf32(acc[1][nt], ah[1], bl[nt]); \
            } \
            _Pragma("unroll") \
            for (int nt = 0; nt < 8; nt++) { \
                mma_tf32(acc[0][nt], al[0], bh[nt]); \
                mma_tf32(acc[1][nt], al[1], bh[nt]); \
            } \
        } \
    } while(0)

    LDG_CHUNK(0);
    STS_CHUNK(0);
    __syncthreads();

    #pragma unroll 1
    for (int c = 0; c < NCHUNK; c++) {
        if (c + 1 < NCHUNK) LDG_CHUNK((c + 1)*KC);
        COMPUTE(c & 1);
        __syncthreads();
        if (c + 1 < NCHUNK) {
            STS_CHUNK((c + 1) & 1);
            __syncthreads();
        }
    }

    // ---- epilogue: GLU on (even,odd) col pairs -> d_g ----
    #pragma unroll
    for (int nt = 0; nt < 8; nt++) {
        const int ch = cB + (nw >> 1) + nt*4 + tig;
        const float bv = bias[ch];
        const float bg = bias[Hh + ch];
        #pragma unroll
        for (int mt = 0; mt < 2; mt++) {
            const int m0 = mB + mw + mt*16 + gid;
            float g0 = (acc[mt][nt][0] + bv) * sigm(acc[mt][nt][1] + bg);
            float g2 = (acc[mt][nt][2] + bv) * sigm(acc[mt][nt][3] + bg);
            d_g[(size_t)m0*Hh + ch]       = g0;
            d_g[(size_t)(m0 + 8)*Hh + ch] = g2;
        }
    }
}

// ---------------- kernel 2: conv + LN + swish + folded pw2/lin -> alphas (2-phase) ----------------
// Phase A: thread = channel, sliding-window conv over CT timesteps -> smem cs.
// Phase B: warp = timestep, butterfly reductions only. 2 barriers total.
__global__ void __launch_bounds__(512)
conv_ln_logit2(const float* __restrict__ dw_w, const float* __restrict__ dw_b,
               const float* __restrict__ ln_g, const float* __restrict__ ln_b,
               const int* __restrict__ x_lens)
{
    extern __shared__ float smc[];
    float* cs = smc;              // [CT][512]
    float* pg = smc + CT*Hh;      // ln_g
    float* pb = pg + Hh;          // ln_b
    float* pw = pb + Hh;          // weff

    const int ch = threadIdx.x;
    const int b  = blockIdx.y;
    const int t0 = blockIdx.x * CT;
    const int lane = ch & 31;
    const int wrp  = ch >> 5;

    // phase A: depthwise conv
    {
        float wk[15];
        #pragma unroll
        for (int k = 0; k < 15; k++) wk[k] = dw_w[ch*Kk + k];
        const float bias = dw_b[ch];
        const float* gb = d_g + (size_t)b*Tt*Hh + ch;

        float win[15];
        #pragma unroll
        for (int k = 0; k < 14; k++) {
            int tg = t0 - 14 + k;
            win[k] = (tg >= 0) ? gb[(size_t)tg*Hh] : 0.0f;
        }
        #pragma unroll 4
        for (int t = 0; t < CT; t++) {
            win[14] = gb[(size_t)(t0 + t)*Hh];
            float c = bias;
            #pragma unroll
            for (int k = 0; k < 15; k++) c = fmaf(win[k], wk[k], c);
            #pragma unroll
            for (int k = 0; k < 14; k++) win[k] = win[k+1];
            cs[t*Hh + ch] = c;
        }
        pg[ch] = ln_g[ch];
        pb[ch] = ln_b[ch];
        pw[ch] = d_weff[ch];
    }
    __syncthreads();

    // phase B: warp handles 2 timesteps; lane handles 16 channels
    const int len  = x_lens[b];
    const float beff = d_beff;
    #pragma unroll
    for (int rep = 0; rep < 2; rep++) {
        const int t = wrp*2 + rep;
        const float* cr = cs + t*Hh + lane*16;
        float4 c4[4];
        #pragma unroll
        for (int q = 0; q < 4; q++) c4[q] = *(const float4*)(cr + q*4);

        float s1 = 0.0f, s2 = 0.0f;
        #pragma unroll
        for (int q = 0; q < 4; q++) {
            const float* cp = (const float*)&c4[q];
            #pragma unroll
            for (int e = 0; e < 4; e++) { s1 += cp[e]; s2 = fmaf(cp[e], cp[e], s2); }
        }
        s1 = bfred(s1);
        s2 = bfred(s2);
        float mean = s1 * (1.0f/512.0f);
        float var  = s2 * (1.0f/512.0f) - mean*mean;
        float rstd = rsqrtf(var + 1e-5f);

        float dot = 0.0f;
        #pragma unroll
        for (int q = 0; q < 4; q++) {
            float4 g4 = *(const float4*)(pg + lane*16 + q*4);
            float4 b4 = *(const float4*)(pb + lane*16 + q*4);
            float4 w4 = *(const float4*)(pw + lane*16 + q*4);
            const float* cp = (const float*)&c4[q];
            const float* gp = (const float*)&g4;
            const float* bp = (const float*)&b4;
            const float* wp = (const float*)&w4;
            #pragma unroll
            for (int e = 0; e < 4; e++) {
                float y  = (cp[e] - mean) * rstd * gp[e] + bp[e];
                float sw = y * sigm(y);
                dot = fmaf(sw, wp[e], dot);
            }
        }
        dot = bfred(dot);
        if (lane == 0) {
            int tg = t0 + t;
            d_alphas[b*Tt + tg] = (tg < len) ? sigm(dot + beff) : 0.0f;
        }
    }
}

// ---------------- kernel 3: per-batch serial CIF scan ----------------
__global__ void scan_kernel()
{
    __shared__ float sa[Tt];
    const int b = blockIdx.x;
    for (int i = threadIdx.x; i < Tt; i += blockDim.x) sa[i] = d_alphas[b*Tt + i];
    __syncthreads();
    if (threadIdx.x == 0) {
        float integ = 0.0f, psum = 0.0f;
        int j = 0;
        for (int t = 0; t < Tt; t++) {
            float a = sa[t];
            psum += a;
            float tt = integ + a;
            bool fire = (tt >= 1.0f);
            if (fire) {
                float dist = 1.0f - integ;
                d_fire_t[b*Tt + j] = t;
                d_dist  [b*Tt + j] = dist;
                d_remain[b*Tt + j] = a - dist;
                j++;
            }
            integ = fire ? (tt - 1.0f) : tt;
        }
        d_nfires[b] = j;
        d_ptn[b] = psum;
    }
}

// ---------------- kernel 4: write all outputs ----------------
__launch_bounds__(128)
__global__ void output_kernel(const float* __restrict__ x, float* __restrict__ out)
{
    const int b   = blockIdx.y;
    const int j   = blockIdx.x;
    const int tid = threadIdx.x;
    float* outF = out;
    float* outP = out + (size_t)Bb*Tt*Hh;
    float* outR = outP + Bb;

    if (j == 0 && tid == 0) outP[b] = d_ptn[b];

    float4 acc = make_float4(0.0f, 0.0f, 0.0f, 0.0f);
    const int nf = d_nfires[b];

    if (j < nf) {
        const float* xb = x + (size_t)b*Tt*Hh + tid*4;
        const int tEnd = d_fire_t[b*Tt + j];
        int t;
        if (j > 0) {
            int   tPrev = d_fire_t[b*Tt + j - 1];
            float wl    = d_remain[b*Tt + j - 1];
            float4 v = *(const float4*)(xb + (size_t)tPrev*Hh);
            acc.x = wl*v.x; acc.y = wl*v.y; acc.z = wl*v.z; acc.w = wl*v.w;
            t = tPrev + 1;
        } else {
            t = 0;
        }
        for (; t < tEnd; t++) {
            float w = d_alphas[b*Tt + t];
            float4 v = *(const float4*)(xb + (size_t)t*Hh);
            acc.x = fmaf(w, v.x, acc.x); acc.y = fmaf(w, v.y, acc.y);
            acc.z = fmaf(w, v.z, acc.z); acc.w = fmaf(w, v.w, acc.w);
        }
        float wd = d_dist[b*Tt + j];
        float4 v = *(const float4*)(xb + (size_t)tEnd*Hh);
        acc.x = fmaf(wd, v.x, acc.x); acc.y = fmaf(wd, v.y, acc.y);
        acc.z = fmaf(wd, v.z, acc.z); acc.w = fmaf(wd, v.w, acc.w);
    }

    *(float4*)(outF + ((size_t)b*Tt + j)*Hh + tid*4) = acc;
    *(float4*)(outR + ((size_t)b*Tt + j)*Hh + (Hh - 4 - tid*4)) =
        make_float4(acc.w, acc.z, acc.y, acc.x);
}

// ---------------- launch ----------------
extern "C" void kernel_launch(void* const* d_in, const int* in_sizes, int n_in,
                              void* d_out, int out_size)
{
    const float* x      = (const float*)d_in[0];
    const int*   x_lens = (const int*)  d_in[1];
    const float* pw1_w  = (const float*)d_in[2];
    const float* pw1_b  = (const float*)d_in[3];
    const float* dw_w   = (const float*)d_in[4];
    const float* dw_b   = (const float*)d_in[5];
    const float* ln_g   = (const float*)d_in[6];
    const float* ln_b   = (const float*)d_in[7];
    const float* pw2_w  = (const float*)d_in[8];
    const float* pw2_b  = (const float*)d_in[9];
    const float* lin_w  = (const float*)d_in[10];
    const float* lin_b  = (const float*)d_in[11];
    float* out = (float*)d_out;

    cudaFuncSetAttribute(gemm_glu_mma,   cudaFuncAttributeMaxDynamicSharedMemorySize, SMEM_GEMM);
    cudaFuncSetAttribute(conv_ln_logit2, cudaFuncAttributeMaxDynamicSharedMemorySize, SMEM_CONV);

    weff_part<<<32, Hh>>>(pw2_w, lin_w);
    weff_sum<<<1, Hh>>>(pw2_b, lin_w, lin_b);
    gemm_glu_mma<<<dim3(8, BT/GM), 256, SMEM_GEMM>>>(x, pw1_w, pw1_b);
    conv_ln_logit2<<<dim3(Tt/CT, Bb), Hh, SMEM_CONV>>>(dw_w, dw_b, ln_g, ln_b, x_lens);
    scan_kernel<<<Bb, 256>>>();
    output_kernel<<<dim3(Tt, Bb), 128>>>(x, out);
}

// round 8
// speedup vs baseline: 1.3261x; 1.0284x over previous
#include <cuda_runtime.h>
#include <math.h>
#include <stdint.h>

#define Bb 16
#define Tt 2048
#define Hh 512
#define Kk 15
#define BT (Bb*Tt)

// ---- GEMM tiling ----
#define GM 128          // M per block
#define GN 128          // interleaved N per block (64 value + 64 gate cols)
#define KC 16           // K per pipeline chunk (halved for 2-block occupancy)
#define NCHUNK (Hh/KC)  // 32
#define LDP 20          // padded row length (words): conflict-free (20r+c mod 32 distinct)
#define BUFS (GM*LDP)   // 2560 words per buffer per stage
// smem: AH[2] AL[2] BH[2] BL[2] -> 8 buffers = 81920 bytes -> 2 blocks/SM
#define SMEM_GEMM (8*BUFS*4)

// ---- conv tiling ----
#define CT 32
#define SMEM_CONV ((CT*Hh + 3*Hh)*4)   // 71680

// ---------------- scratch (__device__ globals) ----------------
__device__ float d_g[(size_t)BT*Hh];   // GLU output (B,T,H) 64MB
__device__ float d_alphas[BT];
__device__ float d_weff[Hh];
__device__ float d_wpart[32*Hh];
__device__ float d_beff;
__device__ int   d_nfires[Bb];
__device__ int   d_fire_t[BT];
__device__ float d_dist[BT];
__device__ float d_remain[BT];
__device__ float d_ptn[Bb];

__device__ __forceinline__ float sigm(float v){ return 1.0f/(1.0f + expf(-v)); }

__device__ __forceinline__ float bfred(float v){
    #pragma unroll
    for (int o = 16; o > 0; o >>= 1) v += __shfl_xor_sync(0xffffffffu, v, o);
    return v;
}

__device__ __forceinline__ uint32_t f2tf32(float v){
    uint32_t r;
    asm("cvt.rna.tf32.f32 %0, %1;" : "=r"(r) : "f"(v));
    return r;
}
__device__ __forceinline__ void tf32_split(float v, uint32_t& h, uint32_t& l){
    h = f2tf32(v);
    l = f2tf32(v - __uint_as_float(h));
}

__device__ __forceinline__ void mma_tf32(float* c, const uint32_t* a, const uint32_t* b){
    asm volatile(
        "mma.sync.aligned.m16n8k8.row.col.f32.tf32.tf32.f32 "
        "{%0,%1,%2,%3}, {%4,%5,%6,%7}, {%8,%9}, {%0,%1,%2,%3};"
        : "+f"(c[0]), "+f"(c[1]), "+f"(c[2]), "+f"(c[3])
        : "r"(a[0]), "r"(a[1]), "r"(a[2]), "r"(a[3]), "r"(b[0]), "r"(b[1]));
}

// ---------------- kernels 0a/0b: fold pw2+lin into w_eff ----------------
__global__ void weff_part(const float* __restrict__ pw2_w, const float* __restrict__ lin_w)
{
    int t = threadIdx.x, j = blockIdx.x;
    float s = 0.0f;
    #pragma unroll
    for (int o = j*16; o < j*16 + 16; o++)
        s = fmaf(lin_w[o], pw2_w[(size_t)o*Hh + t], s);
    d_wpart[j*Hh + t] = s;
}
__global__ void weff_sum(const float* __restrict__ pw2_b, const float* __restrict__ lin_w,
                         const float* __restrict__ lin_b)
{
    int t = threadIdx.x;
    float s = 0.0f;
    #pragma unroll
    for (int j = 0; j < 32; j++) s += d_wpart[j*Hh + t];
    d_weff[t] = s;
    if (t == 0) {
        float bb = lin_b[0];
        for (int o = 0; o < Hh; o++) bb = fmaf(lin_w[o], pw2_b[o], bb);
        d_beff = bb;
    }
}

// ---------------- kernel 1: tf32x3 mma.sync GEMM + GLU (KC=16, 2 blocks/SM) ----------------
__global__ void __launch_bounds__(256, 2)
gemm_glu_mma(const float* __restrict__ x, const float* __restrict__ w,
             const float* __restrict__ bias)
{
    extern __shared__ uint32_t smg[];
    uint32_t* AH = smg;              // [2][BUFS]
    uint32_t* AL = smg + 2*BUFS;
    uint32_t* BH = smg + 4*BUFS;
    uint32_t* BL = smg + 6*BUFS;

    const int tid  = threadIdx.x;
    const int wid  = tid >> 5;
    const int lane = tid & 31;
    const int gid  = lane >> 2;
    const int tig  = lane & 3;
    const int mB = blockIdx.y * GM;
    const int nB = blockIdx.x * GN;
    const int cB = nB >> 1;
    const int mw = (wid & 3) * 32;
    const int nw = (wid >> 2) * 64;

    float acc[2][8][4];
    #pragma unroll
    for (int mt = 0; mt < 2; mt++)
        #pragma unroll
        for (int nt = 0; nt < 8; nt++)
            #pragma unroll
            for (int e = 0; e < 4; e++) acc[mt][nt][e] = 0.0f;

    float4 ra[2], rb[2];

    // A tile: 128 rows x 16 k = 512 float4; 2 per thread. Same for B.
    #define LDG_CHUNK(k0) do { \
        _Pragma("unroll") \
        for (int t = 0; t < 2; t++) { \
            int idx = tid + t*256; \
            int r = idx >> 2, kq = idx & 3; \
            ra[t] = *(const float4*)(x + (size_t)(mB + r)*Hh + (k0) + kq*4); \
            int nq = nB + r; \
            int wr = (nq >> 1) + (nq & 1)*Hh; \
            rb[t] = *(const float4*)(w + (size_t)wr*Hh + (k0) + kq*4); \
        } \
    } while(0)

    #define STS_CHUNK(buf) do { \
        _Pragma("unroll") \
        for (int t = 0; t < 2; t++) { \
            int idx = tid + t*256; \
            int r = idx >> 2, kq = idx & 3; \
            uint32_t o = (buf)*BUFS + r*LDP + kq*4; \
            uint32_t h0,h1,h2,h3,l0,l1,l2,l3; \
            tf32_split(ra[t].x,h0,l0); tf32_split(ra[t].y,h1,l1); \
            tf32_split(ra[t].z,h2,l2); tf32_split(ra[t].w,h3,l3); \
            *(uint4*)(AH + o) = make_uint4(h0,h1,h2,h3); \
            *(uint4*)(AL + o) = make_uint4(l0,l1,l2,l3); \
            tf32_split(rb[t].x,h0,l0); tf32_split(rb[t].y,h1,l1); \
            tf32_split(rb[t].z,h2,l2); tf32_split(rb[t].w,h3,l3); \
            *(uint4*)(BH + o) = make_uint4(h0,h1,h2,h3); \
            *(uint4*)(BL + o) = make_uint4(l0,l1,l2,l3); \
        } \
    } while(0)

    #define COMPUTE(buf) do { \
        const uint32_t* AHp = AH + (buf)*BUFS + mw*LDP; \
        const uint32_t* ALp = AL + (buf)*BUFS + mw*LDP; \
        const uint32_t* BHp = BH + (buf)*BUFS + nw*LDP; \
        const uint32_t* BLp = BL + (buf)*BUFS + nw*LDP; \
        _Pragma("unroll") \
        for (int kk = 0; kk < 2; kk++) { \
            const int kc = kk*8 + tig; \
            uint32_t ah[2][4], al[2][4]; \
            _Pragma("unroll") \
            for (int mt = 0; mt < 2; mt++) { \
                const int r0 = mt*16 + gid; \
                ah[mt][0] = AHp[r0*LDP + kc];         al[mt][0] = ALp[r0*LDP + kc]; \
                ah[mt][1] = AHp[(r0+8)*LDP + kc];     al[mt][1] = ALp[(r0+8)*LDP + kc]; \
                ah[mt][2] = AHp[r0*LDP + kc + 4];     al[mt][2] = ALp[r0*LDP + kc + 4]; \
                ah[mt][3] = AHp[(r0+8)*LDP + kc + 4]; al[mt][3] = ALp[(r0+8)*LDP + kc + 4]; \
            } \
            _Pragma("unroll") \
            for (int ng = 0; ng < 2; ng++) { \
                uint32_t bh[4][2], bl[4][2]; \
                _Pragma("unroll") \
                for (int nt = 0; nt < 4; nt++) { \
                    const int n = (ng*4 + nt)*8 + gid; \
                    bh[nt][0] = BHp[n*LDP + kc];     bl[nt][0] = BLp[n*LDP + kc]; \
                    bh[nt][1] = BHp[n*LDP + kc + 4]; bl[nt][1] = BLp[n*LDP + kc + 4]; \
                } \
                _Pragma("unroll") \
                for (int nt = 0; nt < 4; nt++) { \
                    mma_tf32(acc[0][ng*4+nt], ah[0], bh[nt]); \
                    mma_tf32(acc[1][ng*4+nt], ah[1], bh[nt]); \
                } \
                _Pragma("unroll") \
                for (int nt = 0; nt < 4; nt++) { \
                    mma_tf32(acc[0][ng*4+nt], ah[0], bl[nt]); \
                    mma_tf32(acc[1][ng*4+nt], ah[1], bl[nt]); \
                } \
                _Pragma("unroll") \
                for (int nt = 0; nt < 4; nt++) { \
                    mma_tf32(acc[0][ng*4+nt], al[0], bh[nt]); \
                    mma_tf32(acc[1][ng*4+nt], al[1], bh[nt]); \
                } \
            } \
        } \
    } while(0)

    LDG_CHUNK(0);
    STS_CHUNK(0);
    __syncthreads();

    #pragma unroll 1
    for (int c = 0; c < NCHUNK; c++) {
        if (c + 1 < NCHUNK) LDG_CHUNK((c + 1)*KC);
        COMPUTE(c & 1);
        __syncthreads();
        if (c + 1 < NCHUNK) {
            STS_CHUNK((c + 1) & 1);
            __syncthreads();
        }
    }

    // ---- epilogue: GLU on (even,odd) col pairs -> d_g ----
    #pragma unroll
    for (int nt = 0; nt < 8; nt++) {
        const int ch = cB + (nw >> 1) + nt*4 + tig;
        const float bv = bias[ch];
        const float bg = bias[Hh + ch];
        #pragma unroll
        for (int mt = 0; mt < 2; mt++) {
            const int m0 = mB + mw + mt*16 + gid;
            float g0 = (acc[mt][nt][0] + bv) * sigm(acc[mt][nt][1] + bg);
            float g2 = (acc[mt][nt][2] + bv) * sigm(acc[mt][nt][3] + bg);
            d_g[(size_t)m0*Hh + ch]       = g0;
            d_g[(size_t)(m0 + 8)*Hh + ch] = g2;
        }
    }
}

// ---------------- kernel 2: conv + LN + swish + folded pw2/lin -> alphas (2-phase) ----------------
__global__ void __launch_bounds__(512)
conv_ln_logit2(const float* __restrict__ dw_w, const float* __restrict__ dw_b,
               const float* __restrict__ ln_g, const float* __restrict__ ln_b,
               const int* __restrict__ x_lens)
{
    extern __shared__ float smc[];
    float* cs = smc;              // [CT][512]
    float* pg = smc + CT*Hh;
    float* pb = pg + Hh;
    float* pw = pb + Hh;

    const int ch = threadIdx.x;
    const int b  = blockIdx.y;
    const int t0 = blockIdx.x * CT;
    const int lane = ch & 31;
    const int wrp  = ch >> 5;

    {
        float wk[15];
        #pragma unroll
        for (int k = 0; k < 15; k++) wk[k] = dw_w[ch*Kk + k];
        const float bias = dw_b[ch];
        const float* gb = d_g + (size_t)b*Tt*Hh + ch;

        float win[15];
        #pragma unroll
        for (int k = 0; k < 14; k++) {
            int tg = t0 - 14 + k;
            win[k] = (tg >= 0) ? gb[(size_t)tg*Hh] : 0.0f;
        }
        #pragma unroll 4
        for (int t = 0; t < CT; t++) {
            win[14] = gb[(size_t)(t0 + t)*Hh];
            float c = bias;
            #pragma unroll
            for (int k = 0; k < 15; k++) c = fmaf(win[k], wk[k], c);
            #pragma unroll
            for (int k = 0; k < 14; k++) win[k] = win[k+1];
            cs[t*Hh + ch] = c;
        }
        pg[ch] = ln_g[ch];
        pb[ch] = ln_b[ch];
        pw[ch] = d_weff[ch];
    }
    __syncthreads();

    const int len  = x_lens[b];
    const float beff = d_beff;
    #pragma unroll
    for (int rep = 0; rep < 2; rep++) {
        const int t = wrp*2 + rep;
        const float* cr = cs + t*Hh + lane*16;
        float4 c4[4];
        #pragma unroll
        for (int q = 0; q < 4; q++) c4[q] = *(const float4*)(cr + q*4);

        float s1 = 0.0f, s2 = 0.0f;
        #pragma unroll
        for (int q = 0; q < 4; q++) {
            const float* cp = (const float*)&c4[q];
            #pragma unroll
            for (int e = 0; e < 4; e++) { s1 += cp[e]; s2 = fmaf(cp[e], cp[e], s2); }
        }
        s1 = bfred(s1);
        s2 = bfred(s2);
        float mean = s1 * (1.0f/512.0f);
        float var  = s2 * (1.0f/512.0f) - mean*mean;
        float rstd = rsqrtf(var + 1e-5f);

        float dot = 0.0f;
        #pragma unroll
        for (int q = 0; q < 4; q++) {
            float4 g4 = *(const float4*)(pg + lane*16 + q*4);
            float4 b4 = *(const float4*)(pb + lane*16 + q*4);
            float4 w4 = *(const float4*)(pw + lane*16 + q*4);
            const float* cp = (const float*)&c4[q];
            const float* gp = (const float*)&g4;
            const float* bp = (const float*)&b4;
            const float* wp = (const float*)&w4;
            #pragma unroll
            for (int e = 0; e < 4; e++) {
                float y  = (cp[e] - mean) * rstd * gp[e] + bp[e];
                float sw = y * sigm(y);
                dot = fmaf(sw, wp[e], dot);
            }
        }
        dot = bfred(dot);
        if (lane == 0) {
            int tg = t0 + t;
            d_alphas[b*Tt + tg] = (tg < len) ? sigm(dot + beff) : 0.0f;
        }
    }
}

// ---------------- kernel 3: per-batch serial CIF scan ----------------
__global__ void scan_kernel()
{
    __shared__ float sa[Tt];
    const int b = blockIdx.x;
    for (int i = threadIdx.x; i < Tt; i += blockDim.x) sa[i] = d_alphas[b*Tt + i];
    __syncthreads();
    if (threadIdx.x == 0) {
        float integ = 0.0f, psum = 0.0f;
        int j = 0;
        for (int t = 0; t < Tt; t++) {
            float a = sa[t];
            psum += a;
            float tt = integ + a;
            bool fire = (tt >= 1.0f);
            if (fire) {
                float dist = 1.0f - integ;
                d_fire_t[b*Tt + j] = t;
                d_dist  [b*Tt + j] = dist;
                d_remain[b*Tt + j] = a - dist;
                j++;
            }
            integ = fire ? (tt - 1.0f) : tt;
        }
        d_nfires[b] = j;
        d_ptn[b] = psum;
    }
}

// ---------------- kernel 4: write all outputs ----------------
__launch_bounds__(128)
__global__ void output_kernel(const float* __restrict__ x, float* __restrict__ out)
{
    const int b   = blockIdx.y;
    const int j   = blockIdx.x;
    const int tid = threadIdx.x;
    float* outF = out;
    float* outP = out + (size_t)Bb*Tt*Hh;
    float* outR = outP + Bb;

    if (j == 0 && tid == 0) outP[b] = d_ptn[b];

    float4 acc = make_float4(0.0f, 0.0f, 0.0f, 0.0f);
    const int nf = d_nfires[b];

    if (j < nf) {
        const float* xb = x + (size_t)b*Tt*Hh + tid*4;
        const int tEnd = d_fire_t[b*Tt + j];
        int t;
        if (j > 0) {
            int   tPrev = d_fire_t[b*Tt + j - 1];
            float wl    = d_remain[b*Tt + j - 1];
            float4 v = *(const float4*)(xb + (size_t)tPrev*Hh);
            acc.x = wl*v.x; acc.y = wl*v.y; acc.z = wl*v.z; acc.w = wl*v.w;
            t = tPrev + 1;
        } else {
            t = 0;
        }
        for (; t < tEnd; t++) {
            float w = d_alphas[b*Tt + t];
            float4 v = *(const float4*)(xb + (size_t)t*Hh);
            acc.x = fmaf(w, v.x, acc.x); acc.y = fmaf(w, v.y, acc.y);
            acc.z = fmaf(w, v.z, acc.z); acc.w = fmaf(w, v.w, acc.w);
        }
        float wd = d_dist[b*Tt + j];
        float4 v = *(const float4*)(xb + (size_t)tEnd*Hh);
        acc.x = fmaf(wd, v.x, acc.x); acc.y = fmaf(wd, v.y, acc.y);
        acc.z = fmaf(wd, v.z, acc.z); acc.w = fmaf(wd, v.w, acc.w);
    }

    *(float4*)(outF + ((size_t)b*Tt + j)*Hh + tid*4) = acc;
    *(float4*)(outR + ((size_t)b*Tt + j)*Hh + (Hh - 4 - tid*4)) =
        make_float4(acc.w, acc.z, acc.y, acc.x);
}

// ---------------- launch ----------------
extern "C" void kernel_launch(void* const* d_in, const int* in_sizes, int n_in,
                              void* d_out, int out_size)
{
    const float* x      = (const float*)d_in[0];
    const int*   x_lens = (const int*)  d_in[1];
    const float* pw1_w  = (const float*)d_in[2];
    const float* pw1_b  = (const float*)d_in[3];
    const float* dw_w   = (const float*)d_in[4];
    const float* dw_b   = (const float*)d_in[5];
    const float* ln_g   = (const float*)d_in[6];
    const float* ln_b   = (const float*)d_in[7];
    const float* pw2_w  = (const float*)d_in[8];
    const float* pw2_b  = (const float*)d_in[9];
    const float* lin_w  = (const float*)d_in[10];
    const float* lin_b  = (const float*)d_in[11];
    float* out = (float*)d_out;

    cudaFuncSetAttribute(gemm_glu_mma,   cudaFuncAttributeMaxDynamicSharedMemorySize, SMEM_GEMM);
    cudaFuncSetAttribute(conv_ln_logit2, cudaFuncAttributeMaxDynamicSharedMemorySize, SMEM_CONV);

    weff_part<<<32, Hh>>>(pw2_w, lin_w);
    weff_sum<<<1, Hh>>>(pw2_b, lin_w, lin_b);
    gemm_glu_mma<<<dim3(8, BT/GM), 256, SMEM_GEMM>>>(x, pw1_w, pw1_b);
    conv_ln_logit2<<<dim3(Tt/CT, Bb), Hh, SMEM_CONV>>>(dw_w, dw_b, ln_g, ln_b, x_lens);
    scan_kernel<<<Bb, 256>>>();
    output_kernel<<<dim3(Tt, Bb), 128>>>(x, out);
}

// round 9
// speedup vs baseline: 1.9495x; 1.4701x over previous
#include <cuda_runtime.h>
#include <cuda_fp16.h>
#include <math.h>
#include <stdint.h>

#define Bb 16
#define Tt 2048
#define Hh 512
#define Kk 15
#define BT (Bb*Tt)

// ---- GEMM tiling ----
#define GM 128          // M per block
#define GN 128          // interleaved N per block (64 value + 64 gate cols)
#define KC 16           // K per pipeline chunk (one m16n8k16 step)
#define NCHUNK (Hh/KC)  // 32
#define WPR 12          // words (uint32/half2) per row: 16 halves data + 8 pad -> conflict-free
#define BUFW (GM*WPR)   // 1536 words per buffer per stage
// smem: AH[2] AL[2] BH[2] BL[2] stages -> 8 * 1536 * 4B = 49152
#define SMEM_GEMM (8*BUFW*4)

// ---- conv tiling ----
#define CT 32
#define SMEM_CONV ((CT*Hh + 3*Hh)*4)   // 71680

// ---------------- scratch (__device__ globals) ----------------
__device__ float d_g[(size_t)BT*Hh];   // GLU output (B,T,H) 64MB
__device__ float d_alphas[BT];
__device__ float d_weff[Hh];
__device__ float d_wpart[32*Hh];
__device__ float d_beff;
__device__ int   d_nfires[Bb];
__device__ int   d_fire_t[BT];
__device__ float d_dist[BT];
__device__ float d_remain[BT];
__device__ float d_ptn[Bb];

__device__ __forceinline__ float sigm(float v){ return 1.0f/(1.0f + expf(-v)); }

__device__ __forceinline__ float bfred(float v){
    #pragma unroll
    for (int o = 16; o > 0; o >>= 1) v += __shfl_xor_sync(0xffffffffu, v, o);
    return v;
}

// fp16 hi/lo split: h = rn(v), l = rn(v - h). 11+11 bit mantissa coverage (~tf32x3).
__device__ __forceinline__ void h_split(float v, __half& h, __half& l){
    h = __float2half_rn(v);
    l = __float2half_rn(v - __half2float(h));
}
__device__ __forceinline__ void pack4(const float4& v, uint32_t& hw0, uint32_t& hw1,
                                      uint32_t& lw0, uint32_t& lw1){
    __half hx,lx,hy,ly,hz,lz,hq,lq;
    h_split(v.x,hx,lx); h_split(v.y,hy,ly); h_split(v.z,hz,lz); h_split(v.w,hq,lq);
    __half2 a = __halves2half2(hx,hy); hw0 = *(uint32_t*)&a;
    __half2 b = __halves2half2(hz,hq); hw1 = *(uint32_t*)&b;
    __half2 c = __halves2half2(lx,ly); lw0 = *(uint32_t*)&c;
    __half2 d = __halves2half2(lz,lq); lw1 = *(uint32_t*)&d;
}

__device__ __forceinline__ void mma_f16(float* c, const uint32_t* a, const uint32_t* b){
    asm volatile(
        "mma.sync.aligned.m16n8k16.row.col.f32.f16.f16.f32 "
        "{%0,%1,%2,%3}, {%4,%5,%6,%7}, {%8,%9}, {%0,%1,%2,%3};"
        : "+f"(c[0]), "+f"(c[1]), "+f"(c[2]), "+f"(c[3])
        : "r"(a[0]), "r"(a[1]), "r"(a[2]), "r"(a[3]), "r"(b[0]), "r"(b[1]));
}

// ---------------- kernels 0a/0b: fold pw2+lin into w_eff ----------------
__global__ void weff_part(const float* __restrict__ pw2_w, const float* __restrict__ lin_w)
{
    int t = threadIdx.x, j = blockIdx.x;
    float s = 0.0f;
    #pragma unroll
    for (int o = j*16; o < j*16 + 16; o++)
        s = fmaf(lin_w[o], pw2_w[(size_t)o*Hh + t], s);
    d_wpart[j*Hh + t] = s;
}
__global__ void weff_sum(const float* __restrict__ pw2_b, const float* __restrict__ lin_w,
                         const float* __restrict__ lin_b)
{
    int t = threadIdx.x;
    float s = 0.0f;
    #pragma unroll
    for (int j = 0; j < 32; j++) s += d_wpart[j*Hh + t];
    d_weff[t] = s;
    if (t == 0) {
        float bb = lin_b[0];
        for (int o = 0; o < Hh; o++) bb = fmaf(lin_w[o], pw2_b[o], bb);
        d_beff = bb;
    }
}

// ---------------- kernel 1: fp16x3 mma.sync(k16) GEMM + GLU ----------------
// Fragments are k-contiguous half2 pairs: one LDS.32 per fragment register.
// A rows = tokens (GM), B rows = interleaved value/gate weight cols (GN).
__global__ void __launch_bounds__(256, 2)
gemm_glu_mma(const float* __restrict__ x, const float* __restrict__ w,
             const float* __restrict__ bias)
{
    extern __shared__ uint32_t smg[];
    uint32_t* AH = smg;              // [2][BUFW]
    uint32_t* AL = smg + 2*BUFW;
    uint32_t* BH = smg + 4*BUFW;
    uint32_t* BL = smg + 6*BUFW;

    const int tid  = threadIdx.x;
    const int wid  = tid >> 5;
    const int lane = tid & 31;
    const int gid  = lane >> 2;
    const int tig  = lane & 3;
    const int mB = blockIdx.y * GM;
    const int nB = blockIdx.x * GN;
    const int cB = nB >> 1;
    const int mw = (wid & 3) * 32;   // warp M offset
    const int nw = (wid >> 2) * 64;  // warp N offset (interleaved)

    float acc[2][8][4];
    #pragma unroll
    for (int mt = 0; mt < 2; mt++)
        #pragma unroll
        for (int nt = 0; nt < 8; nt++)
            #pragma unroll
            for (int e = 0; e < 4; e++) acc[mt][nt][e] = 0.0f;

    float4 ra[2], rb[2];

    // per chunk: A tile 128 rows x 16 k = 512 float4 (2/thread); same for B
    #define LDG_CHUNK(k0) do { \
        _Pragma("unroll") \
        for (int t = 0; t < 2; t++) { \
            int idx = tid + t*256; \
            int r = idx >> 2, kq = idx & 3; \
            ra[t] = *(const float4*)(x + (size_t)(mB + r)*Hh + (k0) + kq*4); \
            int nq = nB + r; \
            int wr = (nq >> 1) + (nq & 1)*Hh; \
            rb[t] = *(const float4*)(w + (size_t)wr*Hh + (k0) + kq*4); \
        } \
    } while(0)

    #define STS_CHUNK(buf) do { \
        _Pragma("unroll") \
        for (int t = 0; t < 2; t++) { \
            int idx = tid + t*256; \
            int r = idx >> 2, kq = idx & 3; \
            uint32_t o = (buf)*BUFW + r*WPR + kq*2; \
            uint32_t h0,h1,l0,l1; \
            pack4(ra[t], h0,h1,l0,l1); \
            *(uint2*)(AH + o) = make_uint2(h0,h1); \
            *(uint2*)(AL + o) = make_uint2(l0,l1); \
            pack4(rb[t], h0,h1,l0,l1); \
            *(uint2*)(BH + o) = make_uint2(h0,h1); \
            *(uint2*)(BL + o) = make_uint2(l0,l1); \
        } \
    } while(0)

    // one m16n8k16 K-step per chunk, 3 products (fp16x3)
    #define COMPUTE(buf) do { \
        const uint32_t* AHp = AH + (buf)*BUFW + mw*WPR; \
        const uint32_t* ALp = AL + (buf)*BUFW + mw*WPR; \
        const uint32_t* BHp = BH + (buf)*BUFW + nw*WPR; \
        const uint32_t* BLp = BL + (buf)*BUFW + nw*WPR; \
        uint32_t ah[2][4], al[2][4]; \
        _Pragma("unroll") \
        for (int mt = 0; mt < 2; mt++) { \
            const int r0 = (mt*16 + gid)*WPR; \
            ah[mt][0] = AHp[r0 + tig];           al[mt][0] = ALp[r0 + tig]; \
            ah[mt][1] = AHp[r0 + 8*WPR + tig];   al[mt][1] = ALp[r0 + 8*WPR + tig]; \
            ah[mt][2] = AHp[r0 + tig + 4];       al[mt][2] = ALp[r0 + tig + 4]; \
            ah[mt][3] = AHp[r0 + 8*WPR + tig+4]; al[mt][3] = ALp[r0 + 8*WPR + tig+4]; \
        } \
        _Pragma("unroll") \
        for (int ng = 0; ng < 2; ng++) { \
            uint32_t bh[4][2], bl[4][2]; \
            _Pragma("unroll") \
            for (int nt = 0; nt < 4; nt++) { \
                const int n = ((ng*4 + nt)*8 + gid)*WPR; \
                bh[nt][0] = BHp[n + tig];     bl[nt][0] = BLp[n + tig]; \
                bh[nt][1] = BHp[n + tig + 4]; bl[nt][1] = BLp[n + tig + 4]; \
            } \
            _Pragma("unroll") \
            for (int nt = 0; nt < 4; nt++) { \
                mma_f16(acc[0][ng*4+nt], ah[0], bh[nt]); \
                mma_f16(acc[1][ng*4+nt], ah[1], bh[nt]); \
            } \
            _Pragma("unroll") \
            for (int nt = 0; nt < 4; nt++) { \
                mma_f16(acc[0][ng*4+nt], ah[0], bl[nt]); \
                mma_f16(acc[1][ng*4+nt], ah[1], bl[nt]); \
            } \
            _Pragma("unroll") \
            for (int nt = 0; nt < 4; nt++) { \
                mma_f16(acc[0][ng*4+nt], al[0], bh[nt]); \
                mma_f16(acc[1][ng*4+nt], al[1], bh[nt]); \
            } \
        } \
    } while(0)

    LDG_CHUNK(0);
    STS_CHUNK(0);
    __syncthreads();

    #pragma unroll 1
    for (int c = 0; c < NCHUNK; c++) {
        if (c + 1 < NCHUNK) LDG_CHUNK((c + 1)*KC);
        COMPUTE(c & 1);
        __syncthreads();
        if (c + 1 < NCHUNK) {
            STS_CHUNK((c + 1) & 1);
            __syncthreads();
        }
    }

    // ---- epilogue: GLU on (even,odd) col pairs -> d_g ----
    // C frag: c0=(gid,2tig) c1=(gid,2tig+1) c2=(gid+8,2tig) c3=(gid+8,2tig+1)
    #pragma unroll
    for (int nt = 0; nt < 8; nt++) {
        const int ch = cB + (nw >> 1) + nt*4 + tig;
        const float bv = bias[ch];
        const float bg = bias[Hh + ch];
        #pragma unroll
        for (int mt = 0; mt < 2; mt++) {
            const int m0 = mB + mw + mt*16 + gid;
            float g0 = (acc[mt][nt][0] + bv) * sigm(acc[mt][nt][1] + bg);
            float g2 = (acc[mt][nt][2] + bv) * sigm(acc[mt][nt][3] + bg);
            d_g[(size_t)m0*Hh + ch]       = g0;
            d_g[(size_t)(m0 + 8)*Hh + ch] = g2;
        }
    }
}

// ---------------- kernel 2: conv + LN + swish + folded pw2/lin -> alphas (2-phase) ----------------
__global__ void __launch_bounds__(512)
conv_ln_logit2(const float* __restrict__ dw_w, const float* __restrict__ dw_b,
               const float* __restrict__ ln_g, const float* __restrict__ ln_b,
               const int* __restrict__ x_lens)
{
    extern __shared__ float smc[];
    float* cs = smc;              // [CT][512]
    float* pg = smc + CT*Hh;
    float* pb = pg + Hh;
    float* pw = pb + Hh;

    const int ch = threadIdx.x;
    const int b  = blockIdx.y;
    const int t0 = blockIdx.x * CT;
    const int lane = ch & 31;
    const int wrp  = ch >> 5;

    {
        float wk[15];
        #pragma unroll
        for (int k = 0; k < 15; k++) wk[k] = dw_w[ch*Kk + k];
        const float bias = dw_b[ch];
        const float* gb = d_g + (size_t)b*Tt*Hh + ch;

        float win[15];
        #pragma unroll
        for (int k = 0; k < 14; k++) {
            int tg = t0 - 14 + k;
            win[k] = (tg >= 0) ? gb[(size_t)tg*Hh] : 0.0f;
        }
        #pragma unroll 4
        for (int t = 0; t < CT; t++) {
            win[14] = gb[(size_t)(t0 + t)*Hh];
            float c = bias;
            #pragma unroll
            for (int k = 0; k < 15; k++) c = fmaf(win[k], wk[k], c);
            #pragma unroll
            for (int k = 0; k < 14; k++) win[k] = win[k+1];
            cs[t*Hh + ch] = c;
        }
        pg[ch] = ln_g[ch];
        pb[ch] = ln_b[ch];
        pw[ch] = d_weff[ch];
    }
    __syncthreads();

    const int len  = x_lens[b];
    const float beff = d_beff;
    #pragma unroll
    for (int rep = 0; rep < 2; rep++) {
        const int t = wrp*2 + rep;
        const float* cr = cs + t*Hh + lane*16;
        float4 c4[4];
        #pragma unroll
        for (int q = 0; q < 4; q++) c4[q] = *(const float4*)(cr + q*4);

        float s1 = 0.0f, s2 = 0.0f;
        #pragma unroll
        for (int q = 0; q < 4; q++) {
            const float* cp = (const float*)&c4[q];
            #pragma unroll
            for (int e = 0; e < 4; e++) { s1 += cp[e]; s2 = fmaf(cp[e], cp[e], s2); }
        }
        s1 = bfred(s1);
        s2 = bfred(s2);
        float mean = s1 * (1.0f/512.0f);
        float var  = s2 * (1.0f/512.0f) - mean*mean;
        float rstd = rsqrtf(var + 1e-5f);

        float dot = 0.0f;
        #pragma unroll
        for (int q = 0; q < 4; q++) {
            float4 g4 = *(const float4*)(pg + lane*16 + q*4);
            float4 b4 = *(const float4*)(pb + lane*16 + q*4);
            float4 w4 = *(const float4*)(pw + lane*16 + q*4);
            const float* cp = (const float*)&c4[q];
            const float* gp = (const float*)&g4;
            const float* bp = (const float*)&b4;
            const float* wp = (const float*)&w4;
            #pragma unroll
            for (int e = 0; e < 4; e++) {
                float y  = (cp[e] - mean) * rstd * gp[e] + bp[e];
                float sw = y * sigm(y);
                dot = fmaf(sw, wp[e], dot);
            }
        }
        dot = bfred(dot);
        if (lane == 0) {
            int tg = t0 + t;
            d_alphas[b*Tt + tg] = (tg < len) ? sigm(dot + beff) : 0.0f;
        }
    }
}

// ---------------- kernel 3: per-batch serial CIF scan ----------------
__global__ void scan_kernel()
{
    __shared__ float sa[Tt];
    const int b = blockIdx.x;
    for (int i = threadIdx.x; i < Tt; i += blockDim.x) sa[i] = d_alphas[b*Tt + i];
    __syncthreads();
    if (threadIdx.x == 0) {
        float integ = 0.0f, psum = 0.0f;
        int j = 0;
        for (int t = 0; t < Tt; t++) {
            float a = sa[t];
            psum += a;
            float tt = integ + a;
            bool fire = (tt >= 1.0f);
            if (fire) {
                float dist = 1.0f - integ;
                d_fire_t[b*Tt + j] = t;
                d_dist  [b*Tt + j] = dist;
                d_remain[b*Tt + j] = a - dist;
                j++;
            }
            integ = fire ? (tt - 1.0f) : tt;
        }
        d_nfires[b] = j;
        d_ptn[b] = psum;
    }
}

// ---------------- kernel 4: write all outputs ----------------
__launch_bounds__(128)
__global__ void output_kernel(const float* __restrict__ x, float* __restrict__ out)
{
    const int b   = blockIdx.y;
    const int j   = blockIdx.x;
    const int tid = threadIdx.x;
    float* outF = out;
    float* outP = out + (size_t)Bb*Tt*Hh;
    float* outR = outP + Bb;

    if (j == 0 && tid == 0) outP[b] = d_ptn[b];

    float4 acc = make_float4(0.0f, 0.0f, 0.0f, 0.0f);
    const int nf = d_nfires[b];

    if (j < nf) {
        const float* xb = x + (size_t)b*Tt*Hh + tid*4;
        const int tEnd = d_fire_t[b*Tt + j];
        int t;
        if (j > 0) {
            int   tPrev = d_fire_t[b*Tt + j - 1];
            float wl    = d_remain[b*Tt + j - 1];
            float4 v = *(const float4*)(xb + (size_t)tPrev*Hh);
            acc.x = wl*v.x; acc.y = wl*v.y; acc.z = wl*v.z; acc.w = wl*v.w;
            t = tPrev + 1;
        } else {
            t = 0;
        }
        for (; t < tEnd; t++) {
            float w = d_alphas[b*Tt + t];
            float4 v = *(const float4*)(xb + (size_t)t*Hh);
            acc.x = fmaf(w, v.x, acc.x); acc.y = fmaf(w, v.y, acc.y);
            acc.z = fmaf(w, v.z, acc.z); acc.w = fmaf(w, v.w, acc.w);
        }
        float wd = d_dist[b*Tt + j];
        float4 v = *(const float4*)(xb + (size_t)tEnd*Hh);
        acc.x = fmaf(wd, v.x, acc.x); acc.y = fmaf(wd, v.y, acc.y);
        acc.z = fmaf(wd, v.z, acc.z); acc.w = fmaf(wd, v.w, acc.w);
    }

    *(float4*)(outF + ((size_t)b*Tt + j)*Hh + tid*4) = acc;
    *(float4*)(outR + ((size_t)b*Tt + j)*Hh + (Hh - 4 - tid*4)) =
        make_float4(acc.w, acc.z, acc.y, acc.x);
}

// ---------------- launch ----------------
extern "C" void kernel_launch(void* const* d_in, const int* in_sizes, int n_in,
                              void* d_out, int out_size)
{
    const float* x      = (const float*)d_in[0];
    const int*   x_lens = (const int*)  d_in[1];
    const float* pw1_w  = (const float*)d_in[2];
    const float* pw1_b  = (const float*)d_in[3];
    const float* dw_w   = (const float*)d_in[4];
    const float* dw_b   = (const float*)d_in[5];
    const float* ln_g   = (const float*)d_in[6];
    const float* ln_b   = (const float*)d_in[7];
    const float* pw2_w  = (const float*)d_in[8];
    const float* pw2_b  = (const float*)d_in[9];
    const float* lin_w  = (const float*)d_in[10];
    const float* lin_b  = (const float*)d_in[11];
    float* out = (float*)d_out;

    cudaFuncSetAttribute(gemm_glu_mma,   cudaFuncAttributeMaxDynamicSharedMemorySize, SMEM_GEMM);
    cudaFuncSetAttribute(conv_ln_logit2, cudaFuncAttributeMaxDynamicSharedMemorySize, SMEM_CONV);

    weff_part<<<32, Hh>>>(pw2_w, lin_w);
    weff_sum<<<1, Hh>>>(pw2_b, lin_w, lin_b);
    gemm_glu_mma<<<dim3(8, BT/GM), 256, SMEM_GEMM>>>(x, pw1_w, pw1_b);
    conv_ln_logit2<<<dim3(Tt/CT, Bb), Hh, SMEM_CONV>>>(dw_w, dw_b, ln_g, ln_b, x_lens);
    scan_kernel<<<Bb, 256>>>();
    output_kernel<<<dim3(Tt, Bb), 128>>>(x, out);
}